// round 6
// baseline (speedup 1.0000x reference)
#include <cuda_runtime.h>

// Motion loss: loss_rot + loss_fk + loss_pos, fused single pass + fused reduction.
// B=64, T=2048, J=24, C=4*J+3=99.
//
// Motion-split: thread pairs (lane parity) each run ONE motion's FK chain for a
// given (b,t); diffs exchanged via __shfl_xor. Halves per-thread register state
// (was 128 regs / 21% occ when one thread held both motions).
// FK chain in registers via a 3-slot transform/result pool (topology liveness).
// Fused final reduction via threadfence + fixed-order last-block sum.

#define NB 64
#define NT 2048
#define NJ 24
#define NC 99

#define TPB 128                    // threads per block
#define TPT (TPB / 2)              // t-values per block = 64
#define GX  (NT / TPT)             // 32
#define NBLK (GX * NB)             // 2048 partial sums

__device__ float        g_partial[NBLK];
__device__ unsigned int g_count = 0;

// Slot assignment (A=0,B=1,C=2) from liveness analysis of the chain.
// PSLOT[j] = pool slot holding transform/result of parent(j)  (-1 for root)
// MSLOT[j] = pool slot to store joint j's transform/result into (-1 if leaf)
#define PSLOT_INIT {-1,0,0,0,1,2,0,1,2,0,1,2,0,0,0,1,2,0,2,0,2,0,2,0}
#define MSLOT_INIT { 0,1,2,0,1,2,0,1,2,0,-1,-1,1,2,0,-1,2,0,2,0,2,0,-1,-1}

__device__ __forceinline__ void quat2mat(float w, float x, float y, float z, float* m)
{
    float s = __fdividef(2.0f, w*w + x*x + y*y + z*z);
    float xx = x*x, yy = y*y, zz = z*z;
    float xy = x*y, xz = x*z, yz = y*z;
    float wx = w*x, wy = w*y, wz = w*z;
    m[0] = 1.0f - s*(yy + zz); m[1] = s*(xy - wz);        m[2] = s*(xz + wy);
    m[3] = s*(xy + wz);        m[4] = 1.0f - s*(xx + zz); m[5] = s*(yz - wx);
    m[6] = s*(xz - wy);        m[7] = s*(yz + wx);        m[8] = 1.0f - s*(xx + yy);
}

__device__ __forceinline__ void mm33(const float* a, const float* b, float* c)
{
#pragma unroll
    for (int i = 0; i < 3; ++i)
#pragma unroll
        for (int j = 0; j < 3; ++j)
            c[i*3 + j] = a[i*3 + 0]*b[0*3 + j] + a[i*3 + 1]*b[1*3 + j] + a[i*3 + 2]*b[2*3 + j];
}

__device__ __forceinline__ void mv3(const float* a, const float* v, float* r)
{
#pragma unroll
    for (int i = 0; i < 3; ++i)
        r[i] = a[i*3 + 0]*v[0] + a[i*3 + 1]*v[1] + a[i*3 + 2]*v[2];
}

__global__ __launch_bounds__(TPB)
void motion_loss_kernel(const float* __restrict__ Ym, const float* __restrict__ Xm,
                        const float* __restrict__ Yt, const float* __restrict__ Xt,
                        const float* __restrict__ jw, float* __restrict__ out)
{
    const int b    = blockIdx.y;
    const int tid  = threadIdx.x;
    const int half = tid & 1;                    // 0 = motion Y, 1 = motion X
    const int t    = blockIdx.x * TPT + (tid >> 1);

    __shared__ float offs[2][NJ][3];             // [motion][joint][xyz]
    __shared__ float ws[NJ];

    if (tid < NJ * 3) {
        offs[0][tid / 3][tid % 3] = Yt[b * NJ * 3 + tid];
        offs[1][tid / 3][tid % 3] = Xt[b * NJ * 3 + tid];
    }
    if (tid < NJ) ws[tid] = jw[tid];
    __syncthreads();

    const float* M  = half ? Xm : Ym;
    const float* mb = M + (size_t)b * NC * NT + t;
    const float (*off)[3] = offs[half];

    float accRot = 0.0f, accFk = 0.0f, accPos = 0.0f;

    // 3-slot register pools (single motion): transforms + world positions
    float T[3][9];
    float R[3][3];

    const int PSLOT[NJ] = PSLOT_INIT;
    const int MSLOT[NJ] = MSLOT_INIT;

#pragma unroll
    for (int j = 0; j < NJ; ++j) {
        const int ps = PSLOT[j];
        const int ms = MSLOT[j];

        float q[4];
#pragma unroll
        for (int k = 0; k < 4; ++k)
            q[k] = __ldcs(&mb[(size_t)(4*j + k) * NT]);

        // rot loss: |q - q_partner| (identical in both pair threads; scaled 0.5 later)
        float dRot = 0.0f;
#pragma unroll
        for (int k = 0; k < 4; ++k)
            dRot += fabsf(q[k] - __shfl_xor_sync(0xffffffffu, q[k], 1));
        accRot += ws[j] * dRot;

        float Rm[9];
        quat2mat(q[0], q[1], q[2], q[3], Rm);

        float Tc[9];
        if (ps >= 0) {
            mm33(T[ps], Rm, Tc);
        } else {
#pragma unroll
            for (int k = 0; k < 9; ++k) Tc[k] = Rm[k];
        }

        float r[3];
        mv3(Tc, &off[j][0], r);
        if (ps >= 0) {
#pragma unroll
            for (int k = 0; k < 3; ++k) r[k] += R[ps][k];
        }

        float dFk = 0.0f;
#pragma unroll
        for (int k = 0; k < 3; ++k)
            dFk += fabsf(r[k] - __shfl_xor_sync(0xffffffffu, r[k], 1));
        accFk += ws[j] * dFk;

        if (ms >= 0) {
#pragma unroll
            for (int k = 0; k < 9; ++k) T[ms][k] = Tc[k];
#pragma unroll
            for (int k = 0; k < 3; ++k) R[ms][k] = r[k];
        }
    }

    // position loss: channels 96..98
#pragma unroll
    for (int k = 0; k < 3; ++k) {
        float p = __ldcs(&mb[(size_t)(NC - 3 + k) * NT]);
        accPos += fabsf(p - __shfl_xor_sync(0xffffffffu, p, 1));
    }

    // 0.5: both pair-threads accumulated identical diffs
    const float cRot = 0.5f / ((float)NB * NT * NJ * 4);
    const float cFk  = 0.5f / ((float)NB * NT * NJ * 3);
    const float cPos = 0.5f / ((float)NB * NT * 3);
    float total = accRot * cRot + accFk * cFk + accPos * cPos;

    // block reduction: warp shuffle, then cross-warp via smem
#pragma unroll
    for (int o = 16; o > 0; o >>= 1)
        total += __shfl_down_sync(0xffffffffu, total, o);

    __shared__ float wsum[TPB / 32];
    if ((tid & 31) == 0) wsum[tid >> 5] = total;
    __syncthreads();

    __shared__ bool isLast;
    if (tid == 0) {
        float s = 0.0f;
#pragma unroll
        for (int wgi = 0; wgi < TPB / 32; ++wgi) s += wsum[wgi];
        g_partial[blockIdx.y * gridDim.x + blockIdx.x] = s;
        __threadfence();
        unsigned int prev = atomicAdd(&g_count, 1u);
        isLast = (prev == (unsigned)(NBLK - 1));
    }
    __syncthreads();

    // Last block to arrive reduces all partials in FIXED index order
    // (bit-deterministic regardless of which block runs this).
    if (isLast) {
        float s = 0.0f;
#pragma unroll
        for (int k = 0; k < NBLK / TPB; ++k)
            s += __ldcg(&g_partial[tid * (NBLK / TPB) + k]);

#pragma unroll
        for (int o = 16; o > 0; o >>= 1)
            s += __shfl_down_sync(0xffffffffu, s, o);

        if ((tid & 31) == 0) wsum[tid >> 5] = s;
        __syncthreads();
        if (tid == 0) {
            float r = 0.0f;
#pragma unroll
            for (int wgi = 0; wgi < TPB / 32; ++wgi) r += wsum[wgi];
            out[0] = r;
            g_count = 0;           // reset for next graph replay
            __threadfence();
        }
    }
}

extern "C" void kernel_launch(void* const* d_in, const int* in_sizes, int n_in,
                              void* d_out, int out_size)
{
    const float* Ym = (const float*)d_in[0];
    const float* Xm = (const float*)d_in[1];
    const float* Yt = (const float*)d_in[2];
    const float* Xt = (const float*)d_in[3];
    const float* jw = (const float*)d_in[4];

    dim3 grid(GX, NB);
    motion_loss_kernel<<<grid, TPB>>>(Ym, Xm, Yt, Xt, jw, (float*)d_out);
}